// round 11
// baseline (speedup 1.0000x reference)
#include <cuda_runtime.h>
#include <math.h>

typedef unsigned long long ull;

// Problem constants
#define NB 8
#define SQ 4096
#define EE 1024
#define HH 16
#define NCHUNK 37
#define CSZ_MAX 112

// Scratch (static device globals -- allocation-free per harness rules)
__device__ float g_wqk[HH*EE];
__device__ float g_c[HH];
__device__ float g_logits[NB*HH*SQ];
__device__ float g_pm[NB*HH*SQ];
__device__ float g_A[NB*HH*SQ];
__device__ float g_psum[NB*HH];
__device__ float g_partial[NB*NCHUNK*HH*EE];   // 19.4 MB partial ctx
__device__ float g_ctx[NB*HH*EE];
__device__ float g_hidden[NB*EE];
__device__ float g_act[NB*4*EE];

__device__ __forceinline__ float warp_sum(float v){
    #pragma unroll
    for (int o=16;o;o>>=1) v += __shfl_xor_sync(0xffffffffu, v, o);
    return v;
}

// packed f32x2 helpers
__device__ __forceinline__ void ffma2(ull &d, ull a, ull b){
    asm("fma.rn.f32x2 %0, %1, %2, %0;" : "+l"(d) : "l"(a), "l"(b));
}
__device__ __forceinline__ ull fadd2(ull a, ull b){
    ull d; asm("add.rn.f32x2 %0, %1, %2;" : "=l"(d) : "l"(a), "l"(b)); return d;
}
__device__ __forceinline__ ull pk2(float x, float y){
    float2 t = make_float2(x,y); return *(ull*)&t;
}
__device__ __forceinline__ float2 upk(ull v){ return *(float2*)&v; }

__device__ __forceinline__ void cpa16(void* s, const void* g){
    unsigned sa = (unsigned)__cvta_generic_to_shared(s);
    asm volatile("cp.async.cg.shared.global [%0],[%1],16;"::"r"(sa),"l"(g));
}

// ---------------- K0: q projection (redundant per block) + w_qk e-slice ----------------
__global__ void __launch_bounds__(256) k_wqkf(const float4* __restrict__ Wq4,
                                              const float4* __restrict__ q4,
                                              const float*  __restrict__ bq,
                                              const float*  __restrict__ Wk,
                                              const float*  __restrict__ bk){
    __shared__ float qv[64];
    __shared__ float acc2[128];
    int h = blockIdx.x>>3, es = blockIdx.x&7;
    int tid = threadIdx.x;
    {
        int r = tid>>2, c4 = tid&3;
        int row = h*64 + r;
        float acc = 0.f;
        #pragma unroll 8
        for (int j=0;j<64;j++){
            float4 w = Wq4[row*256 + c4*64 + j];
            float4 q = q4[c4*64 + j];
            acc += w.x*q.x + w.y*q.y + w.z*q.z + w.w*q.w;
        }
        acc += __shfl_xor_sync(0xffffffffu, acc, 1);
        acc += __shfl_xor_sync(0xffffffffu, acc, 2);
        if (c4==0) qv[r] = acc + bq[row];
    }
    __syncthreads();
    {
        int c = tid&127, dh = tid>>7;
        float acc = 0.f;
        #pragma unroll 8
        for (int j=0;j<32;j++){
            int d = dh*32 + j;
            acc += qv[d] * Wk[(h*64+d)*1024 + es*128 + c];
        }
        if (dh==1) acc2[c] = acc;
        __syncthreads();
        if (dh==0)
            g_wqk[h*1024 + es*128 + c] = 0.125f*(acc + acc2[c]);
    }
    if (es==0 && tid==0){
        float c=0.f;
        for (int d=0;d<64;d++) c += qv[d]*bk[h*64+d];
        g_c[h] = 0.125f*c;
    }
}

// ---------------- K1: logits = w_qk·x + c (warp-private pipeline) ----------------
__global__ void __launch_bounds__(256,2) k_logits(const float4* __restrict__ x4){
    __shared__ float4 sxw[8][2][4][32];
    __shared__ float  sred[8][32][16];
    int tid = threadIdx.x, lane = tid&31, warp = tid>>5;
    int hg = lane>>3, ep = lane&7;
    ull wA[4][4], wB[4][4];
    {
        const float4* wq4 = (const float4*)g_wqk;
        #pragma unroll
        for (int k=0;k<4;k++){
            int F = warp*32 + k*8 + ep;
            #pragma unroll
            for (int hp=0;hp<4;hp++){
                float4 wv = wq4[(hg*4+hp)*256 + F];
                wA[k][hp] = pk2(wv.x,wv.y);
                wB[k][hp] = pk2(wv.z,wv.w);
            }
        }
    }
    int rowbase = blockIdx.x*32, b = rowbase>>12;
    bool hi4 = (lane&4)!=0, hi2 = (lane&2)!=0;

    #pragma unroll
    for (int r=0;r<4;r++)
        cpa16(&sxw[warp][0][r][lane], &x4[(rowbase+r)*256 + warp*32 + lane]);
    asm volatile("cp.async.commit_group;");

    for (int t=0;t<8;t++){
        if (t<7){
            int rb1 = rowbase + (t+1)*4;
            #pragma unroll
            for (int r=0;r<4;r++)
                cpa16(&sxw[warp][(t+1)&1][r][lane], &x4[(rb1+r)*256 + warp*32 + lane]);
            asm volatile("cp.async.commit_group;");
            asm volatile("cp.async.wait_group 1;");
        } else {
            asm volatile("cp.async.wait_group 0;");
        }
        __syncwarp();
        const ulonglong2* xs = (const ulonglong2*)&sxw[warp][t&1][0][0] + ep;
        ull acc[4][4];
        #pragma unroll
        for (int r=0;r<4;r++)
            #pragma unroll
            for (int hp=0;hp<4;hp++) acc[r][hp] = 0ULL;
        #pragma unroll
        for (int r=0;r<4;r++){
            #pragma unroll
            for (int k=0;k<4;k++){
                ulonglong2 xu = xs[r*32 + k*8];
                #pragma unroll
                for (int hp=0;hp<4;hp++){
                    ffma2(acc[r][hp], wA[k][hp], xu.x);
                    ffma2(acc[r][hp], wB[k][hp], xu.y);
                }
            }
        }
        #pragma unroll
        for (int r=0;r<4;r++){
            ull s0 = hi4 ? acc[r][0] : acc[r][2];
            s0 = __shfl_xor_sync(0xffffffffu, s0, 4);
            ull a0 = fadd2(hi4 ? acc[r][2] : acc[r][0], s0);
            ull s1 = hi4 ? acc[r][1] : acc[r][3];
            s1 = __shfl_xor_sync(0xffffffffu, s1, 4);
            ull a1 = fadd2(hi4 ? acc[r][3] : acc[r][1], s1);
            ull s2 = hi2 ? a0 : a1;
            s2 = __shfl_xor_sync(0xffffffffu, s2, 2);
            ull aa = fadd2(hi2 ? a1 : a0, s2);
            aa = fadd2(aa, __shfl_xor_sync(0xffffffffu, aa, 1));
            float2 f = upk(aa);
            if ((ep&1)==0) sred[warp][t*4+r][hg*4 + (ep>>1)] = f.x + f.y;
        }
        __syncwarp();
    }
    __syncthreads();
    {
        int h = tid>>5, row = tid&31;
        int sbase = (rowbase&4095) + row;
        #pragma unroll
        for (int hh=0; hh<2; hh++){
            int hc = h + hh*8;
            float s = g_c[hc];
            #pragma unroll
            for (int w=0;w<8;w++) s += sred[w][row][hc];
            g_logits[((b<<4)+hc)*4096 + sbase] = s;
        }
    }
}

// ---------------- K2: softmax over S + gumbel hard mask, per (b,h) ----------------
__global__ void __launch_bounds__(256) k_softmax(const float2* __restrict__ gu2){
    __shared__ float red[8];
    __shared__ float bc;
    int bid = blockIdx.x;                 // b*16+h
    int tid = threadIdx.x, lane = tid&31, warp = tid>>5;
    int base = bid*4096;
    float l[16];
    float m = -1e30f;
    #pragma unroll
    for (int j=0;j<16;j++){ l[j] = g_logits[base + tid + 256*j]; m = fmaxf(m, l[j]); }
    #pragma unroll
    for (int o=16;o;o>>=1) m = fmaxf(m, __shfl_xor_sync(0xffffffffu,m,o));
    if (lane==0) red[warp]=m;
    __syncthreads();
    if (tid==0){ float mm=red[0]; for(int i=1;i<8;i++) mm=fmaxf(mm,red[i]); bc=mm; }
    __syncthreads();
    m = bc;
    float ex[16]; float sum=0.f;
    #pragma unroll
    for (int j=0;j<16;j++){ ex[j]=__expf(l[j]-m); sum+=ex[j]; }
    sum = warp_sum(sum);
    if (lane==0) red[warp]=sum;
    __syncthreads();
    if (tid==0){ float ss=0.f; for(int i=0;i<8;i++) ss+=red[i]; bc=ss; }
    __syncthreads();
    float inv = 1.f/bc;
    float ps=0.f;
    #pragma unroll
    for (int j=0;j<16;j++){
        int s = tid+256*j;
        float prob = ex[j]*inv;
        float2 u = gu2[base+s];
        float g0 = -__logf(-__logf(u.x+1e-20f)+1e-20f);
        float g1 = -__logf(-__logf(u.y+1e-20f)+1e-20f);
        float A = (l[j]+g1 > g0) ? 1.f : 0.f;
        float pm = A*prob;
        g_A[base+s]=A; g_pm[base+s]=pm; ps+=pm;
    }
    ps = warp_sum(ps);
    if (lane==0) red[warp]=ps;
    __syncthreads();
    if (tid==0){ float ss=0.f; for(int i=0;i<8;i++) ss+=red[i]; g_psum[bid]=ss; }
}

// ---------------- K3: ctx partials, e-half split, occ 4 ----------------
// Grid 592 = 8 b x 37 chunks x 2 e-halves = exactly 4 blocks/SM.
// Thread: 4 h-pairs x 4 e-floats -> acc 16 ull (32 regs). Per si:
// 1 LDG.128 (x, own e-half) + 2 LDS.128 (pm pairs, broadcast) + 16 FFMA2.
__global__ void __launch_bounds__(256,4) k_ctx(const float4* __restrict__ x4,
                                               float* __restrict__ out){
    __shared__ __align__(16) ull sp[CSZ_MAX][8];   // (pm[h], pm[h+8]) pairs, 7 KB
    int tid = threadIdx.x;
    int bc = blockIdx.x >> 1, eh = blockIdx.x & 1;
    int b = bc / 37, chunk = bc % 37;
    int c0 = (chunk*4096)/37, c1 = ((chunk+1)*4096)/37;
    int csz = c1 - c0;                    // 110 or 111
    // stage pm pairs (redundant across the 2 e-halves; tiny)
    int slots = csz*8;
    #pragma unroll
    for (int i=0;i<4;i++){
        int idx = tid + 256*i;
        if (idx < slots){
            int si = idx>>3, j = idx&7;
            int s = c0 + si;
            float lo = g_pm[((b<<4)+j  )*4096 + s];
            float hi = g_pm[((b<<4)+j+8)*4096 + s];
            sp[si][j] = pk2(lo, hi);
        }
    }
    // fused masks/attn head-sums (only e-half 0 blocks)
    if (eh==0 && tid < csz){
        int s = c0 + tid;
        float ms=0.f, as=0.f;
        #pragma unroll
        for (int h=0;h<16;h++){
            int off = ((b<<4)+h)*4096 + s;
            ms += g_A[off];
            as += g_pm[off];
        }
        out[8192 + b*4096 + s] = ms;
        out[8192 + 32768 + b*4096 + s] = as;
    }
    __syncthreads();
    int col = tid&127, oct = tid>>7;
    int colg = eh*128 + col;              // global float4 column
    ull acc[4][4];
    #pragma unroll
    for (int j=0;j<4;j++)
        #pragma unroll
        for (int e=0;e<4;e++) acc[j][e] = 0ULL;
    #pragma unroll 8
    for (int si=0; si<csz; si++){
        int row = b*4096 + c0 + si;
        float4 xa = __ldg(&x4[row*256 + colg]);
        ulonglong2 pu01 = *(const ulonglong2*)&sp[si][oct*4];
        ulonglong2 pu23 = *(const ulonglong2*)&sp[si][oct*4+2];
        ull xd0 = pk2(xa.x,xa.x), xd1 = pk2(xa.y,xa.y);
        ull xd2 = pk2(xa.z,xa.z), xd3 = pk2(xa.w,xa.w);
        ffma2(acc[0][0], pu01.x, xd0); ffma2(acc[0][1], pu01.x, xd1);
        ffma2(acc[0][2], pu01.x, xd2); ffma2(acc[0][3], pu01.x, xd3);
        ffma2(acc[1][0], pu01.y, xd0); ffma2(acc[1][1], pu01.y, xd1);
        ffma2(acc[1][2], pu01.y, xd2); ffma2(acc[1][3], pu01.y, xd3);
        ffma2(acc[2][0], pu23.x, xd0); ffma2(acc[2][1], pu23.x, xd1);
        ffma2(acc[2][2], pu23.x, xd2); ffma2(acc[2][3], pu23.x, xd3);
        ffma2(acc[3][0], pu23.y, xd0); ffma2(acc[3][1], pu23.y, xd1);
        ffma2(acc[3][2], pu23.y, xd2); ffma2(acc[3][3], pu23.y, xd3);
    }
    // epilogue: unpack pairs, store both head rows (own e-half only)
    float4* p4 = (float4*)g_partial;
    int pbase = (b*37 + chunk)*16;
    #pragma unroll
    for (int j=0;j<4;j++){
        int hlo = oct*4 + j, hhi = hlo + 8;
        float2 f0 = upk(acc[j][0]), f1 = upk(acc[j][1]);
        float2 f2 = upk(acc[j][2]), f3 = upk(acc[j][3]);
        p4[(pbase+hlo)*256 + colg] = make_float4(f0.x,f1.x,f2.x,f3.x);
        p4[(pbase+hhi)*256 + colg] = make_float4(f0.y,f1.y,f2.y,f3.y);
    }
}

// ---------------- K3r: deterministic reduction of ctx partials (float4) ----------------
__global__ void __launch_bounds__(256) k_ctxr(){
    int f4 = blockIdx.x*256 + threadIdx.x;   // 0..32767 float4 of ctx
    int b = f4>>12, rem = f4&4095;
    const float4* p4 = (const float4*)g_partial;
    float4 s = make_float4(0,0,0,0);
    #pragma unroll
    for (int c=0;c<NCHUNK;c++){
        float4 v = p4[(b*NCHUNK+c)*4096 + rem];
        s.x+=v.x; s.y+=v.y; s.z+=v.z; s.w+=v.w;
    }
    ((float4*)g_ctx)[f4] = s;
}

// ---------------- K4a: hidden = Wv·ctx + bv*psum ----------------
__global__ void __launch_bounds__(256) k_hidden(const float4* __restrict__ Wv4,
                                                const float*  __restrict__ bv){
    int lane = threadIdx.x&31, warp = threadIdx.x>>5;
    int row = blockIdx.x*8+warp;
    int h = row>>6;
    float4 w[8];
    #pragma unroll
    for (int k=0;k<8;k++) w[k] = Wv4[row*256 + lane + 32*k];
    const float4* c4 = (const float4*)g_ctx;
    float acc[8];
    #pragma unroll
    for (int b=0;b<8;b++){
        float s=0.f;
        #pragma unroll
        for (int k=0;k<8;k++){
            float4 c = c4[((b<<4)+h)*256 + lane + 32*k];
            s += w[k].x*c.x + w[k].y*c.y + w[k].z*c.z + w[k].w*c.w;
        }
        acc[b]=s;
    }
    #pragma unroll
    for (int o=16;o;o>>=1)
        #pragma unroll
        for (int b=0;b<8;b++) acc[b] += __shfl_xor_sync(0xffffffffu, acc[b], o);
    if (lane==0){
        float bvr = bv[row];
        #pragma unroll
        for (int b=0;b<8;b++) g_hidden[b*1024+row] = acc[b] + bvr*g_psum[(b<<4)+h];
    }
}

// ---------------- K4c: fused LN + act = relu(ln(hidden) @ W1^T + b1) ----------------
__global__ void __launch_bounds__(256) k_mlp1(const float4* __restrict__ W14,
                                              const float*  __restrict__ b1,
                                              const float4* __restrict__ lg4,
                                              const float4* __restrict__ lb4){
    __shared__ float4 hls[2048];
    int tid = threadIdx.x, lane=tid&31, warp=tid>>5;
    {
        int b = warp;
        const float4* h4 = (const float4*)g_hidden;
        float4 v[8];
        float s = 0.f;
        #pragma unroll
        for (int k=0;k<8;k++){
            v[k] = h4[b*256 + lane + 32*k];
            s += v[k].x + v[k].y + v[k].z + v[k].w;
        }
        s = warp_sum(s);
        float mu = s * (1.f/1024.f);
        float q = 0.f;
        #pragma unroll
        for (int k=0;k<8;k++){
            float dx=v[k].x-mu, dy=v[k].y-mu, dz=v[k].z-mu, dw=v[k].w-mu;
            q += dx*dx + dy*dy + dz*dz + dw*dw;
        }
        q = warp_sum(q);
        float rstd = rsqrtf(q*(1.f/1024.f) + 1e-5f);
        #pragma unroll
        for (int k=0;k<8;k++){
            float4 g = lg4[lane+32*k], bb = lb4[lane+32*k];
            hls[b*256+lane+32*k] = make_float4(
                (v[k].x-mu)*rstd*g.x + bb.x,
                (v[k].y-mu)*rstd*g.y + bb.y,
                (v[k].z-mu)*rstd*g.z + bb.z,
                (v[k].w-mu)*rstd*g.w + bb.w);
        }
    }
    __syncthreads();
    int row = blockIdx.x*8+warp;
    float4 w[8];
    #pragma unroll
    for (int k=0;k<8;k++) w[k]=W14[row*256+lane+32*k];
    float acc[8];
    #pragma unroll
    for (int b=0;b<8;b++){
        float s=0.f;
        #pragma unroll
        for (int k=0;k<8;k++){
            float4 hv = hls[b*256 + lane + 32*k];
            s += w[k].x*hv.x + w[k].y*hv.y + w[k].z*hv.z + w[k].w*hv.w;
        }
        acc[b]=s;
    }
    #pragma unroll
    for (int o=16;o;o>>=1)
        #pragma unroll
        for (int b=0;b<8;b++) acc[b] += __shfl_xor_sync(0xffffffffu, acc[b], o);
    if (lane==0){
        float bb = b1[row];
        #pragma unroll
        for (int b=0;b<8;b++) g_act[b*4096+row] = fmaxf(acc[b]+bb, 0.f);
    }
}

// ---------------- K4d: out = act @ W2^T + b2 ----------------
__global__ void __launch_bounds__(256) k_mlp2(const float4* __restrict__ W24,
                                              const float*  __restrict__ b2,
                                              float* __restrict__ out){
    extern __shared__ float4 as4[];
    int tid=threadIdx.x, lane=tid&31, warp=tid>>5;
    const float4* a4 = (const float4*)g_act;
    #pragma unroll
    for (int i=0;i<32;i++) as4[tid+256*i] = a4[tid+256*i];
    __syncthreads();
    int row = blockIdx.x*8+warp;
    float acc[8];
    #pragma unroll
    for (int b=0;b<8;b++) acc[b]=0.f;
    #pragma unroll 4
    for (int k=0;k<32;k++){
        float4 w = W24[row*1024 + lane + 32*k];
        #pragma unroll
        for (int b=0;b<8;b++){
            float4 av = as4[b*1024 + lane + 32*k];
            acc[b] += w.x*av.x + w.y*av.y + w.z*av.z + w.w*av.w;
        }
    }
    #pragma unroll
    for (int o=16;o;o>>=1)
        #pragma unroll
        for (int b=0;b<8;b++) acc[b] += __shfl_xor_sync(0xffffffffu, acc[b], o);
    if (lane==0){
        float bb = b2[row];
        #pragma unroll
        for (int b=0;b<8;b++) out[b*1024+row] = acc[b] + bb;
    }
}

extern "C" void kernel_launch(void* const* d_in, const int* in_sizes, int n_in,
                              void* d_out, int out_size){
    const float* x     = (const float*)d_in[0];
    const float* gu    = (const float*)d_in[1];
    const float* query = (const float*)d_in[2];
    const float* Wq    = (const float*)d_in[3];
    const float* bq    = (const float*)d_in[4];
    const float* Wk    = (const float*)d_in[5];
    const float* bk    = (const float*)d_in[6];
    const float* Wv    = (const float*)d_in[7];
    const float* bv    = (const float*)d_in[8];
    const float* ln_g  = (const float*)d_in[9];
    const float* ln_b  = (const float*)d_in[10];
    const float* W1    = (const float*)d_in[11];
    const float* b1    = (const float*)d_in[12];
    const float* W2    = (const float*)d_in[13];
    const float* b2    = (const float*)d_in[14];
    float* out = (float*)d_out;

    cudaFuncSetAttribute(k_mlp2, cudaFuncAttributeMaxDynamicSharedMemorySize, 131072);

    k_wqkf   <<<128,256>>>((const float4*)Wq, (const float4*)query, bq,
                           Wk, bk);                                         // 1
    k_logits <<<1024,256>>>((const float4*)x);                              // 2
    k_softmax<<<128,256>>>((const float2*)gu);                              // 3
    k_ctx    <<<592,256>>>((const float4*)x, out);                          // 4 (profiled)
    k_ctxr   <<<128,256>>>();                                               // 5
    k_hidden <<<128,256>>>((const float4*)Wv, bv);                          // 6
    k_mlp1   <<<512,256>>>((const float4*)W1, b1,
                           (const float4*)ln_g, (const float4*)ln_b);       // 7
    k_mlp2   <<<128,256,131072>>>((const float4*)W2, b2, out);              // 8
}

// round 13
// speedup vs baseline: 1.0239x; 1.0239x over previous
#include <cuda_runtime.h>
#include <math.h>

typedef unsigned long long ull;

// Problem constants
#define NB 8
#define SQ 4096
#define EE 1024
#define HH 16
#define NCHUNK 37

// Scratch (static device globals -- allocation-free per harness rules)
__device__ float g_wqk[HH*EE];
__device__ float g_c[HH];
__device__ float g_t[NB*HH*SQ];                 // unnormalized masked exp(l)
__device__ float g_zf[NB*NCHUNK*HH];            // per-chunk sum exp(l)
__device__ float g_zt[NB*NCHUNK*HH];            // per-chunk sum t
__device__ float g_invz[NB*HH];
__device__ float g_psum[NB*HH];
__device__ float g_partial[NB*NCHUNK*HH*EE];    // unnormalized ctx partials
__device__ float g_ctx[NB*HH*EE];
__device__ float g_hidden[NB*EE];
__device__ float g_act[NB*4*EE];

__device__ __forceinline__ float warp_sum(float v){
    #pragma unroll
    for (int o=16;o;o>>=1) v += __shfl_xor_sync(0xffffffffu, v, o);
    return v;
}
__device__ __forceinline__ void ffma2(ull &d, ull a, ull b){
    asm("fma.rn.f32x2 %0, %1, %2, %0;" : "+l"(d) : "l"(a), "l"(b));
}
__device__ __forceinline__ ull fadd2(ull a, ull b){
    ull d; asm("add.rn.f32x2 %0, %1, %2;" : "=l"(d) : "l"(a), "l"(b)); return d;
}
__device__ __forceinline__ ull pk2(float x, float y){
    float2 t = make_float2(x,y); return *(ull*)&t;
}
__device__ __forceinline__ float2 upk(ull v){ return *(float2*)&v; }
__device__ __forceinline__ void cpa16(void* s, const void* g){
    unsigned sa = (unsigned)__cvta_generic_to_shared(s);
    asm volatile("cp.async.cg.shared.global [%0],[%1],16;"::"r"(sa),"l"(g));
}
__device__ __forceinline__ int imin(int a, int b){ return a<b?a:b; }

__global__ void k_dummy(){}

// ---------------- K0: q projection + w_qk e-slice (grid 128) ----------------
__global__ void __launch_bounds__(256) k_wqkf(const float4* __restrict__ Wq4,
                                              const float4* __restrict__ q4,
                                              const float*  __restrict__ bq,
                                              const float*  __restrict__ Wk,
                                              const float*  __restrict__ bk){
    __shared__ float qv[64];
    __shared__ float acc2[128];
    int h = blockIdx.x>>3, es = blockIdx.x&7;
    int tid = threadIdx.x;
    {
        int r = tid>>2, c4 = tid&3;
        int row = h*64 + r;
        float acc = 0.f;
        #pragma unroll 8
        for (int j=0;j<64;j++){
            float4 w = Wq4[row*256 + c4*64 + j];
            float4 q = q4[c4*64 + j];
            acc += w.x*q.x + w.y*q.y + w.z*q.z + w.w*q.w;
        }
        acc += __shfl_xor_sync(0xffffffffu, acc, 1);
        acc += __shfl_xor_sync(0xffffffffu, acc, 2);
        if (c4==0) qv[r] = acc + bq[row];
    }
    __syncthreads();
    {
        int c = tid&127, dh = tid>>7;
        float acc = 0.f;
        #pragma unroll 8
        for (int j=0;j<32;j++){
            int d = dh*32 + j;
            acc += qv[d] * Wk[(h*64+d)*1024 + es*128 + c];
        }
        if (dh==1) acc2[c] = acc;
        __syncthreads();
        if (dh==0)
            g_wqk[h*1024 + es*128 + c] = 0.125f*(acc + acc2[c]);
    }
    if (es==0 && tid==0){
        float c=0.f;
        for (int d=0;d<64;d++) c += qv[d]*bk[h*64+d];
        g_c[h] = 0.125f*c;
    }
}

// ---------------- K1: FUSED logits+gumbel+ctx, single pass over x ----------------
// Per block: (b, chunk of ~111 s-rows). Phase A (2 halves of 56 rows): warp-private
// logits pipeline (R8 structure) -> combine: t = A*exp(l) into smem st + g_t,
// per-chunk Z partials. Phase B: ctx partial accumulation from triple-buffered
// cp.async x tiles (L2-hot re-read) using st. Normalization deferred to k_ctxr.
__global__ void __launch_bounds__(256,2) k_fused(const float4* __restrict__ x4,
                                                 const float2* __restrict__ gu2){
    extern __shared__ char dyn[];
    float4* xA   = (float4*)dyn;                    // A: [8][2][4][32] (32KB of 48KB region)
    float4* xB   = (float4*)dyn;                    // B: [3][4][256] (48KB)
    float*  sred = (float*)(dyn + 49152);           // [8][56][16] = 28.7KB
    ull*    st   = (ull*)(dyn + 77824);             // [112][8] = 7KB, pairs (h,h+8)
    float2* zfp  = (float2*)(dyn + 84992);          // [16][16]

    int tid = threadIdx.x, lane = tid&31, warp = tid>>5;
    int hg = lane>>3, ep = lane&7;
    int b = blockIdx.x/37, chunk = blockIdx.x%37;
    int c0 = (chunk*4096)/37, c1 = ((chunk+1)*4096)/37;
    int xrow0 = b*4096;

    // weights in regs (R8 layout)
    ull wA[4][4], wB[4][4];
    {
        const float4* wq4 = (const float4*)g_wqk;
        #pragma unroll
        for (int k=0;k<4;k++){
            int F = warp*32 + k*8 + ep;
            #pragma unroll
            for (int hp=0;hp<4;hp++){
                float4 wv = wq4[(hg*4+hp)*256 + F];
                wA[k][hp] = pk2(wv.x,wv.y);
                wB[k][hp] = pk2(wv.z,wv.w);
            }
        }
    }
    bool hi4 = (lane&4)!=0, hi2 = (lane&2)!=0;
    int ch = tid>>4, rg = tid&15;       // combine role: head ch, row-group rg
    float zf_acc = 0.f, zt_acc = 0.f;

    for (int half=0; half<2; half++){
        int base_s = c0 + half*56;
        // ---- phase A: warp-private logits over 14 4-row tiles ----
        #pragma unroll
        for (int r=0;r<4;r++){
            int s = imin(base_s + r, c1-1);
            cpa16(&xA[((warp*2+0)*4+r)*32+lane], &x4[(xrow0+s)*256 + warp*32+lane]);
        }
        asm volatile("cp.async.commit_group;");
        for (int t=0;t<14;t++){
            if (t<13){
                #pragma unroll
                for (int r=0;r<4;r++){
                    int s = imin(base_s + (t+1)*4 + r, c1-1);
                    cpa16(&xA[((warp*2+((t+1)&1))*4+r)*32+lane], &x4[(xrow0+s)*256 + warp*32+lane]);
                }
                asm volatile("cp.async.commit_group;");
                asm volatile("cp.async.wait_group 1;");
            } else {
                asm volatile("cp.async.wait_group 0;");
            }
            __syncwarp();
            const ulonglong2* xs = (const ulonglong2*)&xA[((warp*2+(t&1))*4)*32] + ep;
            ull acc[4][4];
            #pragma unroll
            for (int r=0;r<4;r++)
                #pragma unroll
                for (int hp=0;hp<4;hp++) acc[r][hp] = 0ULL;
            #pragma unroll
            for (int r=0;r<4;r++){
                #pragma unroll
                for (int k=0;k<4;k++){
                    ulonglong2 xu = xs[r*32 + k*8];
                    #pragma unroll
                    for (int hp=0;hp<4;hp++){
                        ffma2(acc[r][hp], wA[k][hp], xu.x);
                        ffma2(acc[r][hp], wB[k][hp], xu.y);
                    }
                }
            }
            #pragma unroll
            for (int r=0;r<4;r++){
                ull s0 = hi4 ? acc[r][0] : acc[r][2];
                s0 = __shfl_xor_sync(0xffffffffu, s0, 4);
                ull a0 = fadd2(hi4 ? acc[r][2] : acc[r][0], s0);
                ull s1 = hi4 ? acc[r][1] : acc[r][3];
                s1 = __shfl_xor_sync(0xffffffffu, s1, 4);
                ull a1 = fadd2(hi4 ? acc[r][3] : acc[r][1], s1);
                ull s2 = hi2 ? a0 : a1;
                s2 = __shfl_xor_sync(0xffffffffu, s2, 2);
                ull aa = fadd2(hi2 ? a1 : a0, s2);
                aa = fadd2(aa, __shfl_xor_sync(0xffffffffu, aa, 1));
                float2 f = upk(aa);
                if ((ep&1)==0) sred[(warp*56 + t*4+r)*16 + hg*4 + (ep>>1)] = f.x + f.y;
            }
            __syncwarp();
        }
        __syncthreads();
        // ---- combine: l -> gumbel -> t ----
        {
            float cc = g_c[ch];
            for (int r = rg; r < 56; r += 16){
                float l = cc;
                #pragma unroll
                for (int w=0;w<8;w++) l += sred[(w*56+r)*16 + ch];
                int sg = base_s + r;
                bool valid = sg < c1;
                float ex = __expf(l);
                float2 u = gu2[(b*16+ch)*4096 + imin(sg, c1-1)];
                float g0 = -__logf(-__logf(u.x+1e-20f)+1e-20f);
                float g1 = -__logf(-__logf(u.y+1e-20f)+1e-20f);
                float tval = (l+g1 > g0) ? ex : 0.f;
                float tw = valid ? tval : 0.f;
                ((float*)st)[(half*56+r)*16 + (ch&7)*2 + (ch>>3)] = tw;
                if (valid){
                    zf_acc += ex;
                    zt_acc += tval;
                    g_t[(b*16+ch)*4096 + sg] = tval;
                }
            }
        }
        __syncthreads();
    }
    // per-chunk Z partials
    zfp[ch*16+rg] = make_float2(zf_acc, zt_acc);
    __syncthreads();
    if (tid < 16){
        float zf=0.f, zt=0.f;
        #pragma unroll
        for (int r=0;r<16;r++){ float2 v = zfp[tid*16+r]; zf+=v.x; zt+=v.y; }
        g_zf[(b*37+chunk)*16 + tid] = zf;
        g_zt[(b*37+chunk)*16 + tid] = zt;
    }
    __syncthreads();

    // ---- phase B: ctx partials from x (L2-hot), triple-buffered ----
    int c = tid&127, oct = tid>>7;
    ull acc[4][8];
    #pragma unroll
    for (int j=0;j<4;j++)
        #pragma unroll
        for (int e=0;e<8;e++) acc[j][e] = 0ULL;

    #pragma unroll
    for (int r=0;r<4;r++){
        int s = imin(c0 + r, c1-1);
        cpa16(&xB[(0*4+r)*256 + tid], &x4[(xrow0+s)*256 + tid]);
    }
    asm volatile("cp.async.commit_group;");
    #pragma unroll
    for (int r=0;r<4;r++){
        int s = imin(c0 + 4 + r, c1-1);
        cpa16(&xB[(1*4+r)*256 + tid], &x4[(xrow0+s)*256 + tid]);
    }
    asm volatile("cp.async.commit_group;");

    for (int t=0;t<28;t++){
        if (t<27) asm volatile("cp.async.wait_group 1;");
        else      asm volatile("cp.async.wait_group 0;");
        __syncthreads();
        int buf = t%3;
        #pragma unroll
        for (int si=0; si<4; si++){
            int row = t*4+si;
            float4 xa = xB[(buf*4+si)*256 + c];
            float4 xb = xB[(buf*4+si)*256 + 128 + c];
            ulonglong2 p01 = *(const ulonglong2*)&st[row*8 + oct*4];
            ulonglong2 p23 = *(const ulonglong2*)&st[row*8 + oct*4+2];
            ull pu0=p01.x, pu1=p01.y, pu2=p23.x, pu3=p23.y;
            ull xd0=pk2(xa.x,xa.x), xd1=pk2(xa.y,xa.y), xd2=pk2(xa.z,xa.z), xd3=pk2(xa.w,xa.w);
            ull xd4=pk2(xb.x,xb.x), xd5=pk2(xb.y,xb.y), xd6=pk2(xb.z,xb.z), xd7=pk2(xb.w,xb.w);
            ffma2(acc[0][0],pu0,xd0); ffma2(acc[0][1],pu0,xd1); ffma2(acc[0][2],pu0,xd2); ffma2(acc[0][3],pu0,xd3);
            ffma2(acc[0][4],pu0,xd4); ffma2(acc[0][5],pu0,xd5); ffma2(acc[0][6],pu0,xd6); ffma2(acc[0][7],pu0,xd7);
            ffma2(acc[1][0],pu1,xd0); ffma2(acc[1][1],pu1,xd1); ffma2(acc[1][2],pu1,xd2); ffma2(acc[1][3],pu1,xd3);
            ffma2(acc[1][4],pu1,xd4); ffma2(acc[1][5],pu1,xd5); ffma2(acc[1][6],pu1,xd6); ffma2(acc[1][7],pu1,xd7);
            ffma2(acc[2][0],pu2,xd0); ffma2(acc[2][1],pu2,xd1); ffma2(acc[2][2],pu2,xd2); ffma2(acc[2][3],pu2,xd3);
            ffma2(acc[2][4],pu2,xd4); ffma2(acc[2][5],pu2,xd5); ffma2(acc[2][6],pu2,xd6); ffma2(acc[2][7],pu2,xd7);
            ffma2(acc[3][0],pu3,xd0); ffma2(acc[3][1],pu3,xd1); ffma2(acc[3][2],pu3,xd2); ffma2(acc[3][3],pu3,xd3);
            ffma2(acc[3][4],pu3,xd4); ffma2(acc[3][5],pu3,xd5); ffma2(acc[3][6],pu3,xd6); ffma2(acc[3][7],pu3,xd7);
        }
        if (t+2 < 28){
            int buf2 = (t+2)%3;
            #pragma unroll
            for (int r=0;r<4;r++){
                int s = imin(c0 + (t+2)*4 + r, c1-1);
                cpa16(&xB[(buf2*4+r)*256 + tid], &x4[(xrow0+s)*256 + tid]);
            }
            asm volatile("cp.async.commit_group;");
        }
    }
    // epilogue: unnormalized partials
    float4* p4 = (float4*)g_partial;
    int pbase = (b*37 + chunk)*16;
    #pragma unroll
    for (int j=0;j<4;j++){
        int hlo = oct*4 + j, hhi = hlo + 8;
        float2 f0=upk(acc[j][0]), f1=upk(acc[j][1]), f2=upk(acc[j][2]), f3=upk(acc[j][3]);
        float2 f4v=upk(acc[j][4]), f5=upk(acc[j][5]), f6=upk(acc[j][6]), f7=upk(acc[j][7]);
        p4[(pbase+hlo)*256 + c]       = make_float4(f0.x,f1.x,f2.x,f3.x);
        p4[(pbase+hlo)*256 + 128 + c] = make_float4(f4v.x,f5.x,f6.x,f7.x);
        p4[(pbase+hhi)*256 + c]       = make_float4(f0.y,f1.y,f2.y,f3.y);
        p4[(pbase+hhi)*256 + 128 + c] = make_float4(f4v.y,f5.y,f6.y,f7.y);
    }
}

// ---------------- K2: finalize Z (1 block) ----------------
__global__ void __launch_bounds__(128) k_finz(){
    int bh = threadIdx.x;            // b*16+h
    int b = bh>>4, h = bh&15;
    float zf=0.f, zt=0.f;
    #pragma unroll
    for (int c=0;c<NCHUNK;c++){
        zf += g_zf[(b*37+c)*16 + h];
        zt += g_zt[(b*37+c)*16 + h];
    }
    float iz = 1.f/zf;
    g_invz[bh] = iz;
    g_psum[bh] = zt*iz;
}

// ---------------- K3: reduce ctx partials, normalize by invZ ----------------
__global__ void __launch_bounds__(256) k_ctxr(){
    int f4 = blockIdx.x*256 + threadIdx.x;   // b*4096 + h*256 + e4
    int b = f4>>12, h = (f4>>8)&15, rem = f4&4095;
    float iz = g_invz[(b<<4)+h];
    const float4* p4 = (const float4*)g_partial;
    float4 s = make_float4(0,0,0,0);
    #pragma unroll
    for (int c=0;c<NCHUNK;c++){
        float4 v = p4[((b*37+c)<<12) + rem];
        s.x+=v.x; s.y+=v.y; s.z+=v.z; s.w+=v.w;
    }
    s.x*=iz; s.y*=iz; s.z*=iz; s.w*=iz;
    ((float4*)g_ctx)[f4] = s;
}

// ---------------- K4: masks/attn outputs from t ----------------
__global__ void __launch_bounds__(256) k_att(float* __restrict__ out){
    int idx = blockIdx.x*256 + threadIdx.x;  // b*4096+s
    int b = idx>>12, s = idx&4095;
    float ms=0.f, as=0.f;
    #pragma unroll
    for (int h=0;h<16;h++){
        float tv = g_t[((b<<4)+h)*4096 + s];
        ms += (tv>0.f) ? 1.f : 0.f;
        as += tv*g_invz[(b<<4)+h];
    }
    out[8192 + idx] = ms;
    out[8192 + 32768 + idx] = as;
}

// ---------------- K5: hidden = Wv·ctx + bv*psum ----------------
__global__ void __launch_bounds__(256) k_hidden(const float4* __restrict__ Wv4,
                                                const float*  __restrict__ bv){
    int lane = threadIdx.x&31, warp = threadIdx.x>>5;
    int row = blockIdx.x*8+warp;
    int h = row>>6;
    float4 w[8];
    #pragma unroll
    for (int k=0;k<8;k++) w[k] = Wv4[row*256 + lane + 32*k];
    const float4* c4 = (const float4*)g_ctx;
    float acc[8];
    #pragma unroll
    for (int b=0;b<8;b++){
        float s=0.f;
        #pragma unroll
        for (int k=0;k<8;k++){
            float4 c = c4[((b<<4)+h)*256 + lane + 32*k];
            s += w[k].x*c.x + w[k].y*c.y + w[k].z*c.z + w[k].w*c.w;
        }
        acc[b]=s;
    }
    #pragma unroll
    for (int o=16;o;o>>=1)
        #pragma unroll
        for (int b=0;b<8;b++) acc[b] += __shfl_xor_sync(0xffffffffu, acc[b], o);
    if (lane==0){
        float bvr = bv[row];
        #pragma unroll
        for (int b=0;b<8;b++) g_hidden[b*1024+row] = acc[b] + bvr*g_psum[(b<<4)+h];
    }
}

// ---------------- K6: fused LN + act = relu(ln(hidden) @ W1^T + b1) ----------------
__global__ void __launch_bounds__(256) k_mlp1(const float4* __restrict__ W14,
                                              const float*  __restrict__ b1,
                                              const float4* __restrict__ lg4,
                                              const float4* __restrict__ lb4){
    __shared__ float4 hls[2048];
    int tid = threadIdx.x, lane=tid&31, warp=tid>>5;
    {
        int b = warp;
        const float4* h4 = (const float4*)g_hidden;
        float4 v[8];
        float s = 0.f;
        #pragma unroll
        for (int k=0;k<8;k++){
            v[k] = h4[b*256 + lane + 32*k];
            s += v[k].x + v[k].y + v[k].z + v[k].w;
        }
        s = warp_sum(s);
        float mu = s * (1.f/1024.f);
        float q = 0.f;
        #pragma unroll
        for (int k=0;k<8;k++){
            float dx=v[k].x-mu, dy=v[k].y-mu, dz=v[k].z-mu, dw=v[k].w-mu;
            q += dx*dx + dy*dy + dz*dz + dw*dw;
        }
        q = warp_sum(q);
        float rstd = rsqrtf(q*(1.f/1024.f) + 1e-5f);
        #pragma unroll
        for (int k=0;k<8;k++){
            float4 g = lg4[lane+32*k], bb = lb4[lane+32*k];
            hls[b*256+lane+32*k] = make_float4(
                (v[k].x-mu)*rstd*g.x + bb.x,
                (v[k].y-mu)*rstd*g.y + bb.y,
                (v[k].z-mu)*rstd*g.z + bb.z,
                (v[k].w-mu)*rstd*g.w + bb.w);
        }
    }
    __syncthreads();
    int row = blockIdx.x*8+warp;
    float4 w[8];
    #pragma unroll
    for (int k=0;k<8;k++) w[k]=W14[row*256+lane+32*k];
    float acc[8];
    #pragma unroll
    for (int b=0;b<8;b++){
        float s=0.f;
        #pragma unroll
        for (int k=0;k<8;k++){
            float4 hv = hls[b*256 + lane + 32*k];
            s += w[k].x*hv.x + w[k].y*hv.y + w[k].z*hv.z + w[k].w*hv.w;
        }
        acc[b]=s;
    }
    #pragma unroll
    for (int o=16;o;o>>=1)
        #pragma unroll
        for (int b=0;b<8;b++) acc[b] += __shfl_xor_sync(0xffffffffu, acc[b], o);
    if (lane==0){
        float bb = b1[row];
        #pragma unroll
        for (int b=0;b<8;b++) g_act[b*4096+row] = fmaxf(acc[b]+bb, 0.f);
    }
}

// ---------------- K7: out = act @ W2^T + b2 ----------------
__global__ void __launch_bounds__(256) k_mlp2(const float4* __restrict__ W24,
                                              const float*  __restrict__ b2,
                                              float* __restrict__ out){
    extern __shared__ float4 as4[];
    int tid=threadIdx.x, lane=tid&31, warp=tid>>5;
    const float4* a4 = (const float4*)g_act;
    #pragma unroll
    for (int i=0;i<32;i++) as4[tid+256*i] = a4[tid+256*i];
    __syncthreads();
    int row = blockIdx.x*8+warp;
    float acc[8];
    #pragma unroll
    for (int b=0;b<8;b++) acc[b]=0.f;
    #pragma unroll 4
    for (int k=0;k<32;k++){
        float4 w = W24[row*1024 + lane + 32*k];
        #pragma unroll
        for (int b=0;b<8;b++){
            float4 av = as4[b*1024 + lane + 32*k];
            acc[b] += w.x*av.x + w.y*av.y + w.z*av.z + w.w*av.w;
        }
    }
    #pragma unroll
    for (int o=16;o;o>>=1)
        #pragma unroll
        for (int b=0;b<8;b++) acc[b] += __shfl_xor_sync(0xffffffffu, acc[b], o);
    if (lane==0){
        float bb = b2[row];
        #pragma unroll
        for (int b=0;b<8;b++) out[b*1024+row] = acc[b] + bb;
    }
}

extern "C" void kernel_launch(void* const* d_in, const int* in_sizes, int n_in,
                              void* d_out, int out_size){
    const float* x     = (const float*)d_in[0];
    const float* gu    = (const float*)d_in[1];
    const float* query = (const float*)d_in[2];
    const float* Wq    = (const float*)d_in[3];
    const float* bq    = (const float*)d_in[4];
    const float* Wk    = (const float*)d_in[5];
    const float* bk    = (const float*)d_in[6];
    const float* Wv    = (const float*)d_in[7];
    const float* bv    = (const float*)d_in[8];
    const float* ln_g  = (const float*)d_in[9];
    const float* ln_b  = (const float*)d_in[10];
    const float* W1    = (const float*)d_in[11];
    const float* b1    = (const float*)d_in[12];
    const float* W2    = (const float*)d_in[13];
    const float* b2    = (const float*)d_in[14];
    float* out = (float*)d_out;

    cudaFuncSetAttribute(k_fused, cudaFuncAttributeMaxDynamicSharedMemorySize, 87040);
    cudaFuncSetAttribute(k_mlp2,  cudaFuncAttributeMaxDynamicSharedMemorySize, 131072);

    k_wqkf  <<<128,256>>>((const float4*)Wq, (const float4*)query, bq, Wk, bk); // 1
    k_dummy <<<1,32>>>();                                                       // 2
    k_dummy <<<1,32>>>();                                                       // 3
    k_fused <<<296,256,87040>>>((const float4*)x, (const float2*)gu);           // 4 (profiled)
    k_finz  <<<1,128>>>();                                                      // 5
    k_ctxr  <<<128,256>>>();                                                    // 6
    k_att   <<<128,256>>>(out);                                                 // 7
    k_hidden<<<128,256>>>((const float4*)Wv, bv);                               // 8
    k_mlp1  <<<512,256>>>((const float4*)W1, b1,
                          (const float4*)ln_g, (const float4*)ln_b);            // 9
    k_mlp2  <<<128,256,131072>>>((const float4*)W2, b2, out);                   // 10
}

// round 16
// speedup vs baseline: 1.0897x; 1.0643x over previous
#include <cuda_runtime.h>
#include <math.h>

typedef unsigned long long ull;

// Problem constants
#define NB 8
#define SQ 4096
#define EE 1024
#define HH 16
#define NCHUNK 37

// Scratch (static device globals -- allocation-free per harness rules)
__device__ float g_wqk[HH*EE];
__device__ float g_c[HH];
__device__ float g_t[NB*HH*SQ];                 // unnormalized masked exp(l)
__device__ float g_zf[NB*NCHUNK*HH];            // per-chunk sum exp(l)
__device__ float g_zt[NB*NCHUNK*HH];            // per-chunk sum t
__device__ float g_invz[NB*HH];
__device__ float g_partial[NB*NCHUNK*HH*EE];    // unnormalized ctx partials
__device__ float g_hidden[NB*EE];
__device__ float g_act[NB*4*EE];

__device__ __forceinline__ float warp_sum(float v){
    #pragma unroll
    for (int o=16;o;o>>=1) v += __shfl_xor_sync(0xffffffffu, v, o);
    return v;
}
__device__ __forceinline__ void ffma2(ull &d, ull a, ull b){
    asm("fma.rn.f32x2 %0, %1, %2, %0;" : "+l"(d) : "l"(a), "l"(b));
}
__device__ __forceinline__ ull fadd2(ull a, ull b){
    ull d; asm("add.rn.f32x2 %0, %1, %2;" : "=l"(d) : "l"(a), "l"(b)); return d;
}
__device__ __forceinline__ ull pk2(float x, float y){
    float2 t = make_float2(x,y); return *(ull*)&t;
}
__device__ __forceinline__ float2 upk(ull v){ return *(float2*)&v; }
__device__ __forceinline__ void cpa16(void* s, const void* g){
    unsigned sa = (unsigned)__cvta_generic_to_shared(s);
    asm volatile("cp.async.cg.shared.global [%0],[%1],16;"::"r"(sa),"l"(g));
}
__device__ __forceinline__ int imin(int a, int b){ return a<b?a:b; }

// ---------------- K0: q projection + w_qk e-slice (grid 128) ----------------
__global__ void __launch_bounds__(256) k_wqkf(const float4* __restrict__ Wq4,
                                              const float4* __restrict__ q4,
                                              const float*  __restrict__ bq,
                                              const float*  __restrict__ Wk,
                                              const float*  __restrict__ bk){
    __shared__ float qv[64];
    __shared__ float acc2[128];
    int h = blockIdx.x>>3, es = blockIdx.x&7;
    int tid = threadIdx.x;
    {
        int r = tid>>2, c4 = tid&3;
        int row = h*64 + r;
        float acc = 0.f;
        #pragma unroll 8
        for (int j=0;j<64;j++){
            float4 w = Wq4[row*256 + c4*64 + j];
            float4 q = q4[c4*64 + j];
            acc += w.x*q.x + w.y*q.y + w.z*q.z + w.w*q.w;
        }
        acc += __shfl_xor_sync(0xffffffffu, acc, 1);
        acc += __shfl_xor_sync(0xffffffffu, acc, 2);
        if (c4==0) qv[r] = acc + bq[row];
    }
    __syncthreads();
    {
        int c = tid&127, dh = tid>>7;
        float acc = 0.f;
        #pragma unroll 8
        for (int j=0;j<32;j++){
            int d = dh*32 + j;
            acc += qv[d] * Wk[(h*64+d)*1024 + es*128 + c];
        }
        if (dh==1) acc2[c] = acc;
        __syncthreads();
        if (dh==0)
            g_wqk[h*1024 + es*128 + c] = 0.125f*(acc + acc2[c]);
    }
    if (es==0 && tid==0){
        float c=0.f;
        for (int d=0;d<64;d++) c += qv[d]*bk[h*64+d];
        g_c[h] = 0.125f*c;
    }
}

// ---------------- K1: FUSED logits+gumbel+ctx, single pass over x ----------------
__global__ void __launch_bounds__(256,2) k_fused(const float4* __restrict__ x4,
                                                 const float2* __restrict__ gu2){
    extern __shared__ char dyn[];
    float4* xA   = (float4*)dyn;                    // A: [8][2][4][32] (32KB of 48KB region)
    float4* xB   = (float4*)dyn;                    // B: [3][4][256] (48KB)
    float*  sred = (float*)(dyn + 49152);           // [8][56][16] = 28.7KB
    ull*    st   = (ull*)(dyn + 77824);             // [112][8] = 7KB, pairs (h,h+8)
    float2* zfp  = (float2*)(dyn + 84992);          // [16][16]

    int tid = threadIdx.x, lane = tid&31, warp = tid>>5;
    int hg = lane>>3, ep = lane&7;
    int b = blockIdx.x/37, chunk = blockIdx.x%37;
    int c0 = (chunk*4096)/37, c1 = ((chunk+1)*4096)/37;
    int xrow0 = b*4096;

    ull wA[4][4], wB[4][4];
    {
        const float4* wq4 = (const float4*)g_wqk;
        #pragma unroll
        for (int k=0;k<4;k++){
            int F = warp*32 + k*8 + ep;
            #pragma unroll
            for (int hp=0;hp<4;hp++){
                float4 wv = wq4[(hg*4+hp)*256 + F];
                wA[k][hp] = pk2(wv.x,wv.y);
                wB[k][hp] = pk2(wv.z,wv.w);
            }
        }
    }
    bool hi4 = (lane&4)!=0, hi2 = (lane&2)!=0;
    int ch = tid>>4, rg = tid&15;
    float zf_acc = 0.f, zt_acc = 0.f;

    for (int half=0; half<2; half++){
        int base_s = c0 + half*56;
        #pragma unroll
        for (int r=0;r<4;r++){
            int s = imin(base_s + r, c1-1);
            cpa16(&xA[((warp*2+0)*4+r)*32+lane], &x4[(xrow0+s)*256 + warp*32+lane]);
        }
        asm volatile("cp.async.commit_group;");
        for (int t=0;t<14;t++){
            if (t<13){
                #pragma unroll
                for (int r=0;r<4;r++){
                    int s = imin(base_s + (t+1)*4 + r, c1-1);
                    cpa16(&xA[((warp*2+((t+1)&1))*4+r)*32+lane], &x4[(xrow0+s)*256 + warp*32+lane]);
                }
                asm volatile("cp.async.commit_group;");
                asm volatile("cp.async.wait_group 1;");
            } else {
                asm volatile("cp.async.wait_group 0;");
            }
            __syncwarp();
            const ulonglong2* xs = (const ulonglong2*)&xA[((warp*2+(t&1))*4)*32] + ep;
            ull acc[4][4];
            #pragma unroll
            for (int r=0;r<4;r++)
                #pragma unroll
                for (int hp=0;hp<4;hp++) acc[r][hp] = 0ULL;
            #pragma unroll
            for (int r=0;r<4;r++){
                #pragma unroll
                for (int k=0;k<4;k++){
                    ulonglong2 xu = xs[r*32 + k*8];
                    #pragma unroll
                    for (int hp=0;hp<4;hp++){
                        ffma2(acc[r][hp], wA[k][hp], xu.x);
                        ffma2(acc[r][hp], wB[k][hp], xu.y);
                    }
                }
            }
            #pragma unroll
            for (int r=0;r<4;r++){
                ull s0 = hi4 ? acc[r][0] : acc[r][2];
                s0 = __shfl_xor_sync(0xffffffffu, s0, 4);
                ull a0 = fadd2(hi4 ? acc[r][2] : acc[r][0], s0);
                ull s1 = hi4 ? acc[r][1] : acc[r][3];
                s1 = __shfl_xor_sync(0xffffffffu, s1, 4);
                ull a1 = fadd2(hi4 ? acc[r][3] : acc[r][1], s1);
                ull s2 = hi2 ? a0 : a1;
                s2 = __shfl_xor_sync(0xffffffffu, s2, 2);
                ull aa = fadd2(hi2 ? a1 : a0, s2);
                aa = fadd2(aa, __shfl_xor_sync(0xffffffffu, aa, 1));
                float2 f = upk(aa);
                if ((ep&1)==0) sred[(warp*56 + t*4+r)*16 + hg*4 + (ep>>1)] = f.x + f.y;
            }
            __syncwarp();
        }
        __syncthreads();
        // combine: l -> gumbel -> t
        {
            float cc = g_c[ch];
            for (int r = rg; r < 56; r += 16){
                float l = cc;
                #pragma unroll
                for (int w=0;w<8;w++) l += sred[(w*56+r)*16 + ch];
                int sg = base_s + r;
                bool valid = sg < c1;
                float ex = __expf(l);
                float2 u = gu2[(b*16+ch)*4096 + imin(sg, c1-1)];
                float g0 = -__logf(-__logf(u.x+1e-20f)+1e-20f);
                float g1 = -__logf(-__logf(u.y+1e-20f)+1e-20f);
                float tval = (l+g1 > g0) ? ex : 0.f;
                float tw = valid ? tval : 0.f;
                ((float*)st)[(half*56+r)*16 + (ch&7)*2 + (ch>>3)] = tw;
                if (valid){
                    zf_acc += ex;
                    zt_acc += tval;
                    g_t[(b*16+ch)*4096 + sg] = tval;
                }
            }
        }
        __syncthreads();
    }
    zfp[ch*16+rg] = make_float2(zf_acc, zt_acc);
    __syncthreads();
    if (tid < 16){
        float zf=0.f, zt=0.f;
        #pragma unroll
        for (int r=0;r<16;r++){ float2 v = zfp[tid*16+r]; zf+=v.x; zt+=v.y; }
        g_zf[(b*37+chunk)*16 + tid] = zf;
        g_zt[(b*37+chunk)*16 + tid] = zt;
    }
    __syncthreads();

    // phase B: ctx partials from x (L2-hot), triple-buffered
    int c = tid&127, oct = tid>>7;
    ull acc[4][8];
    #pragma unroll
    for (int j=0;j<4;j++)
        #pragma unroll
        for (int e=0;e<8;e++) acc[j][e] = 0ULL;

    #pragma unroll
    for (int r=0;r<4;r++){
        int s = imin(c0 + r, c1-1);
        cpa16(&xB[(0*4+r)*256 + tid], &x4[(xrow0+s)*256 + tid]);
    }
    asm volatile("cp.async.commit_group;");
    #pragma unroll
    for (int r=0;r<4;r++){
        int s = imin(c0 + 4 + r, c1-1);
        cpa16(&xB[(1*4+r)*256 + tid], &x4[(xrow0+s)*256 + tid]);
    }
    asm volatile("cp.async.commit_group;");

    for (int t=0;t<28;t++){
        if (t<27) asm volatile("cp.async.wait_group 1;");
        else      asm volatile("cp.async.wait_group 0;");
        __syncthreads();
        int buf = t%3;
        #pragma unroll
        for (int si=0; si<4; si++){
            int row = t*4+si;
            float4 xa = xB[(buf*4+si)*256 + c];
            float4 xb = xB[(buf*4+si)*256 + 128 + c];
            ulonglong2 p01 = *(const ulonglong2*)&st[row*8 + oct*4];
            ulonglong2 p23 = *(const ulonglong2*)&st[row*8 + oct*4+2];
            ull pu0=p01.x, pu1=p01.y, pu2=p23.x, pu3=p23.y;
            ull xd0=pk2(xa.x,xa.x), xd1=pk2(xa.y,xa.y), xd2=pk2(xa.z,xa.z), xd3=pk2(xa.w,xa.w);
            ull xd4=pk2(xb.x,xb.x), xd5=pk2(xb.y,xb.y), xd6=pk2(xb.z,xb.z), xd7=pk2(xb.w,xb.w);
            ffma2(acc[0][0],pu0,xd0); ffma2(acc[0][1],pu0,xd1); ffma2(acc[0][2],pu0,xd2); ffma2(acc[0][3],pu0,xd3);
            ffma2(acc[0][4],pu0,xd4); ffma2(acc[0][5],pu0,xd5); ffma2(acc[0][6],pu0,xd6); ffma2(acc[0][7],pu0,xd7);
            ffma2(acc[1][0],pu1,xd0); ffma2(acc[1][1],pu1,xd1); ffma2(acc[1][2],pu1,xd2); ffma2(acc[1][3],pu1,xd3);
            ffma2(acc[1][4],pu1,xd4); ffma2(acc[1][5],pu1,xd5); ffma2(acc[1][6],pu1,xd6); ffma2(acc[1][7],pu1,xd7);
            ffma2(acc[2][0],pu2,xd0); ffma2(acc[2][1],pu2,xd1); ffma2(acc[2][2],pu2,xd2); ffma2(acc[2][3],pu2,xd3);
            ffma2(acc[2][4],pu2,xd4); ffma2(acc[2][5],pu2,xd5); ffma2(acc[2][6],pu2,xd6); ffma2(acc[2][7],pu2,xd7);
            ffma2(acc[3][0],pu3,xd0); ffma2(acc[3][1],pu3,xd1); ffma2(acc[3][2],pu3,xd2); ffma2(acc[3][3],pu3,xd3);
            ffma2(acc[3][4],pu3,xd4); ffma2(acc[3][5],pu3,xd5); ffma2(acc[3][6],pu3,xd6); ffma2(acc[3][7],pu3,xd7);
        }
        if (t+2 < 28){
            int buf2 = (t+2)%3;
            #pragma unroll
            for (int r=0;r<4;r++){
                int s = imin(c0 + (t+2)*4 + r, c1-1);
                cpa16(&xB[(buf2*4+r)*256 + tid], &x4[(xrow0+s)*256 + tid]);
            }
            asm volatile("cp.async.commit_group;");
        }
    }
    float4* p4 = (float4*)g_partial;
    int pbase = (b*37 + chunk)*16;
    #pragma unroll
    for (int j=0;j<4;j++){
        int hlo = oct*4 + j, hhi = hlo + 8;
        float2 f0=upk(acc[j][0]), f1=upk(acc[j][1]), f2=upk(acc[j][2]), f3=upk(acc[j][3]);
        float2 f4v=upk(acc[j][4]), f5=upk(acc[j][5]), f6=upk(acc[j][6]), f7=upk(acc[j][7]);
        p4[(pbase+hlo)*256 + c]       = make_float4(f0.x,f1.x,f2.x,f3.x);
        p4[(pbase+hlo)*256 + 128 + c] = make_float4(f4v.x,f5.x,f6.x,f7.x);
        p4[(pbase+hhi)*256 + c]       = make_float4(f0.y,f1.y,f2.y,f3.y);
        p4[(pbase+hhi)*256 + 128 + c] = make_float4(f4v.y,f5.y,f6.y,f7.y);
    }
}

// ---------------- K2: MERGED ctx-reduce + finalize-Z + hidden (grid 128 = b*16+h) ----------------
__global__ void __launch_bounds__(256) k_ctxrh(const float4* __restrict__ Wv4,
                                               const float*  __restrict__ bv){
    __shared__ float4 ctxs[256];       // normalized ctx row [1024 floats]
    __shared__ float zbuf[2*NCHUNK];
    __shared__ float izs, pss;
    int tid = threadIdx.x, lane = tid&31, warp = tid>>5;
    int bh = blockIdx.x, b = bh>>4, h = bh&15;

    if (tid < NCHUNK){
        zbuf[tid]        = g_zf[(b*37+tid)*16 + h];
        zbuf[NCHUNK+tid] = g_zt[(b*37+tid)*16 + h];
    }
    __syncthreads();
    if (tid == 0){
        float zf=0.f, zt=0.f;
        #pragma unroll
        for (int c=0;c<NCHUNK;c++){ zf += zbuf[c]; zt += zbuf[NCHUNK+c]; }
        float iz = 1.f/zf;
        izs = iz; pss = zt*iz;
        g_invz[bh] = iz;
    }
    __syncthreads();
    float iz = izs, ps = pss;
    // reduce 37 partials for this (b,h) row, normalize
    {
        const float4* p4 = (const float4*)g_partial;
        int off = h*256 + tid;
        float4 s = make_float4(0,0,0,0);
        #pragma unroll
        for (int c=0;c<NCHUNK;c++){
            float4 v = p4[((b*37+c)<<12) + off];
            s.x+=v.x; s.y+=v.y; s.z+=v.z; s.w+=v.w;
        }
        s.x*=iz; s.y*=iz; s.z*=iz; s.w*=iz;
        ctxs[tid] = s;
    }
    __syncthreads();
    // hidden rows h*64 .. h*64+63: 8 warps x 8 rows
    #pragma unroll
    for (int rr=0; rr<8; rr++){
        int row = h*64 + warp*8 + rr;
        float acc = 0.f;
        #pragma unroll
        for (int k=0;k<8;k++){
            float4 w = Wv4[row*256 + lane + 32*k];
            float4 cv = ctxs[lane + 32*k];
            acc += w.x*cv.x + w.y*cv.y + w.z*cv.z + w.w*cv.w;
        }
        acc = warp_sum(acc);
        if (lane==0) g_hidden[b*1024+row] = acc + bv[row]*ps;
    }
}

// ---------------- K3: masks/attn outputs from t ----------------
__global__ void __launch_bounds__(256) k_att(float* __restrict__ out){
    int idx = blockIdx.x*256 + threadIdx.x;  // b*4096+s
    int b = idx>>12, s = idx&4095;
    float ms=0.f, as=0.f;
    #pragma unroll
    for (int h=0;h<16;h++){
        float tv = g_t[((b<<4)+h)*4096 + s];
        ms += (tv>0.f) ? 1.f : 0.f;
        as += tv*g_invz[(b<<4)+h];
    }
    out[8192 + idx] = ms;
    out[8192 + 32768 + idx] = as;
}

// ---------------- K4: fused LN + act = relu(ln(hidden) @ W1^T + b1) ----------------
__global__ void __launch_bounds__(256) k_mlp1(const float4* __restrict__ W14,
                                              const float*  __restrict__ b1,
                                              const float4* __restrict__ lg4,
                                              const float4* __restrict__ lb4){
    __shared__ float4 hls[2048];
    int tid = threadIdx.x, lane=tid&31, warp=tid>>5;
    {
        int b = warp;
        const float4* h4 = (const float4*)g_hidden;
        float4 v[8];
        float s = 0.f;
        #pragma unroll
        for (int k=0;k<8;k++){
            v[k] = h4[b*256 + lane + 32*k];
            s += v[k].x + v[k].y + v[k].z + v[k].w;
        }
        s = warp_sum(s);
        float mu = s * (1.f/1024.f);
        float q = 0.f;
        #pragma unroll
        for (int k=0;k<8;k++){
            float dx=v[k].x-mu, dy=v[k].y-mu, dz=v[k].z-mu, dw=v[k].w-mu;
            q += dx*dx + dy*dy + dz*dz + dw*dw;
        }
        q = warp_sum(q);
        float rstd = rsqrtf(q*(1.f/1024.f) + 1e-5f);
        #pragma unroll
        for (int k=0;k<8;k++){
            float4 g = lg4[lane+32*k], bb = lb4[lane+32*k];
            hls[b*256+lane+32*k] = make_float4(
                (v[k].x-mu)*rstd*g.x + bb.x,
                (v[k].y-mu)*rstd*g.y + bb.y,
                (v[k].z-mu)*rstd*g.z + bb.z,
                (v[k].w-mu)*rstd*g.w + bb.w);
        }
    }
    __syncthreads();
    int row = blockIdx.x*8+warp;
    float4 w[8];
    #pragma unroll
    for (int k=0;k<8;k++) w[k]=W14[row*256+lane+32*k];
    float acc[8];
    #pragma unroll
    for (int b=0;b<8;b++){
        float s=0.f;
        #pragma unroll
        for (int k=0;k<8;k++){
            float4 hv = hls[b*256 + lane + 32*k];
            s += w[k].x*hv.x + w[k].y*hv.y + w[k].z*hv.z + w[k].w*hv.w;
        }
        acc[b]=s;
    }
    #pragma unroll
    for (int o=16;o;o>>=1)
        #pragma unroll
        for (int b=0;b<8;b++) acc[b] += __shfl_xor_sync(0xffffffffu, acc[b], o);
    if (lane==0){
        float bb = b1[row];
        #pragma unroll
        for (int b=0;b<8;b++) g_act[b*4096+row] = fmaxf(acc[b]+bb, 0.f);
    }
}

// ---------------- K5: out = act @ W2^T + b2 ----------------
__global__ void __launch_bounds__(256) k_mlp2(const float4* __restrict__ W24,
                                              const float*  __restrict__ b2,
                                              float* __restrict__ out){
    extern __shared__ float4 as4[];
    int tid=threadIdx.x, lane=tid&31, warp=tid>>5;
    const float4* a4 = (const float4*)g_act;
    #pragma unroll
    for (int i=0;i<32;i++) as4[tid+256*i] = a4[tid+256*i];
    __syncthreads();
    int row = blockIdx.x*8+warp;
    float acc[8];
    #pragma unroll
    for (int b=0;b<8;b++) acc[b]=0.f;
    #pragma unroll 4
    for (int k=0;k<32;k++){
        float4 w = W24[row*1024 + lane + 32*k];
        #pragma unroll
        for (int b=0;b<8;b++){
            float4 av = as4[b*1024 + lane + 32*k];
            acc[b] += w.x*av.x + w.y*av.y + w.z*av.z + w.w*av.w;
        }
    }
    #pragma unroll
    for (int o=16;o;o>>=1)
        #pragma unroll
        for (int b=0;b<8;b++) acc[b] += __shfl_xor_sync(0xffffffffu, acc[b], o);
    if (lane==0){
        float bb = b2[row];
        #pragma unroll
        for (int b=0;b<8;b++) out[b*1024+row] = acc[b] + bb;
    }
}

extern "C" void kernel_launch(void* const* d_in, const int* in_sizes, int n_in,
                              void* d_out, int out_size){
    const float* x     = (const float*)d_in[0];
    const float* gu    = (const float*)d_in[1];
    const float* query = (const float*)d_in[2];
    const float* Wq    = (const float*)d_in[3];
    const float* bq    = (const float*)d_in[4];
    const float* Wk    = (const float*)d_in[5];
    const float* bk    = (const float*)d_in[6];
    const float* Wv    = (const float*)d_in[7];
    const float* bv    = (const float*)d_in[8];
    const float* ln_g  = (const float*)d_in[9];
    const float* ln_b  = (const float*)d_in[10];
    const float* W1    = (const float*)d_in[11];
    const float* b1    = (const float*)d_in[12];
    const float* W2    = (const float*)d_in[13];
    const float* b2    = (const float*)d_in[14];
    float* out = (float*)d_out;

    cudaFuncSetAttribute(k_fused, cudaFuncAttributeMaxDynamicSharedMemorySize, 87040);
    cudaFuncSetAttribute(k_mlp2,  cudaFuncAttributeMaxDynamicSharedMemorySize, 131072);

    k_wqkf  <<<128,256>>>((const float4*)Wq, (const float4*)query, bq, Wk, bk); // 1
    k_fused <<<296,256,87040>>>((const float4*)x, (const float2*)gu);           // 2
    k_ctxrh <<<128,256>>>((const float4*)Wv, bv);                               // 3
    k_att   <<<128,256>>>(out);                                                 // 4 (profiled)
    k_mlp1  <<<512,256>>>((const float4*)W1, b1,
                          (const float4*)ln_g, (const float4*)ln_b);            // 5
    k_mlp2  <<<128,256,131072>>>((const float4*)W2, b2, out);                   // 6
}